// round 13
// baseline (speedup 1.0000x reference)
#include <cuda_runtime.h>
#include <cuda_bf16.h>
#include <cuda_fp16.h>
#include <cstdint>
#include <math.h>

// ---------------------------------------------------------------------------
// IPMTrans round 13:
//   precomp    -> 8B descriptors (packed addrs + fp16 weights): halved L2 traffic
//   sampler    -> per-channel G=1, 64KB smem planes
//   GEMM       -> mma.sync bf16 3-pass, <64,128> BK=64, 2-stage cp.async,
//                 warp grid 2x4 (MT=2,NT=4: 20% less ldsm per MMA)
//   3 streams  -> per-scale chains
// ---------------------------------------------------------------------------

#define BVAL 2
#define SVAL 4
#define YVAL 4

// ------------------------- scratch (device globals) ------------------------
__device__ __align__(16) __nv_bfloat16 g_v2hi[2u * 1024u * 4096u];
__device__ __align__(16) __nv_bfloat16 g_v2lo[2u * 1024u * 4096u];
__device__ __align__(16) __nv_bfloat16 g_v4hi[2u * 2048u * 1024u];
__device__ __align__(16) __nv_bfloat16 g_v4lo[2u * 2048u * 1024u];
__device__ __align__(16) __nv_bfloat16 g_v8hi[2u * 4096u * 256u];
__device__ __align__(16) __nv_bfloat16 g_v8lo[2u * 4096u * 256u];
__device__ __align__(16) __nv_bfloat16 g_w2hi[256u * 1024u];
__device__ __align__(16) __nv_bfloat16 g_w2lo[256u * 1024u];
__device__ __align__(16) __nv_bfloat16 g_w4hi[512u * 2048u];
__device__ __align__(16) __nv_bfloat16 g_w4lo[512u * 2048u];
__device__ __align__(16) __nv_bfloat16 g_w8hi[1024u * 4096u];
__device__ __align__(16) __nv_bfloat16 g_w8lo[1024u * 4096u];
__device__ __align__(16) uint2 g_pre2[8u * 16384u];
__device__ __align__(16) uint2 g_pre4[8u * 4096u];
__device__ __align__(16) uint2 g_pre8[8u * 1024u];

// ------------------------- PTX helpers -------------------------------------
__device__ __forceinline__ uint32_t smem_u32(const void* p) {
    uint32_t a;
    asm("{ .reg .u64 t; cvta.to.shared.u64 t, %1; cvt.u32.u64 %0, t; }" : "=r"(a) : "l"(p));
    return a;
}
__device__ __forceinline__ void cp16(uint32_t dst, const void* src) {
    asm volatile("cp.async.cg.shared.global [%0], [%1], 16;" :: "r"(dst), "l"(src));
}
#define CP_COMMIT() asm volatile("cp.async.commit_group;" ::: "memory")
#define CP_WAIT1()  asm volatile("cp.async.wait_group 1;" ::: "memory")

__device__ __forceinline__ void ldsm4(uint32_t* r, uint32_t addr) {
    asm volatile("ldmatrix.sync.aligned.m8n8.x4.shared.b16 {%0,%1,%2,%3}, [%4];"
        : "=r"(r[0]), "=r"(r[1]), "=r"(r[2]), "=r"(r[3]) : "r"(addr));
}
__device__ __forceinline__ void ldsm4t(uint32_t* r, uint32_t addr) {
    asm volatile("ldmatrix.sync.aligned.m8n8.x4.trans.shared.b16 {%0,%1,%2,%3}, [%4];"
        : "=r"(r[0]), "=r"(r[1]), "=r"(r[2]), "=r"(r[3]) : "r"(addr));
}
__device__ __forceinline__ void mma16816(float* d, const uint32_t* a, const uint32_t* b) {
    asm volatile(
        "mma.sync.aligned.m16n8k16.row.col.f32.bf16.bf16.f32 "
        "{%0,%1,%2,%3}, {%4,%5,%6,%7}, {%8,%9}, {%0,%1,%2,%3};"
        : "+f"(d[0]), "+f"(d[1]), "+f"(d[2]), "+f"(d[3])
        : "r"(a[0]), "r"(a[1]), "r"(a[2]), "r"(a[3]), "r"(b[0]), "r"(b[1]));
}

// ---------------------------------------------------------------------------
// Kernel P: precompute 8B gather descriptors.
//   pre.x = a0 | dx<<15 | a1<<16 ; sentinel HW when invalid
//   pre.y = fp16(wx) | fp16(wy)<<16   (wx=wy=0 when invalid)
// ---------------------------------------------------------------------------
__global__ void precomp_kernel(const float* __restrict__ coords,
                               uint2* __restrict__ pre,
                               int Wd, int total)
{
    int i = blockIdx.x * blockDim.x + threadIdx.x;
    if (i >= total) return;
    float2 g = ((const float2*)coords)[i];
    const int HW = Wd * Wd;
    const float sc = 0.5f * (float)(Wd - 1);

    float ix = (g.x + 1.0f) * sc;
    float iy = (g.y + 1.0f) * sc;
    float x0f = floorf(ix);
    float y0f = floorf(iy);
    float wx = ix - x0f;
    float wy = iy - y0f;
    int x0 = min(max((int)x0f, 0), Wd - 1);
    int y0 = min(max((int)y0f, 0), Wd - 1);
    int x1 = min(x0 + 1, Wd - 1);
    int y1 = min(y0 + 1, Wd - 1);
    bool valid = (g.x >= -1.0f) & (g.x <= 1.0f) & (g.y >= -1.0f) & (g.y <= 1.0f);

    int a0 = y0 * Wd + x0;
    int a1 = y1 * Wd + x0;
    int dx = x1 - x0;
    if (!valid) { a0 = HW; a1 = HW; dx = 0; wx = 0.0f; wy = 0.0f; }

    unsigned short hx = __half_as_ushort(__float2half_rn(wx));
    unsigned short hy = __half_as_ushort(__float2half_rn(wy));
    pre[i] = make_uint2((uint32_t)a0 | ((uint32_t)dx << 15) | ((uint32_t)a1 << 16),
                        (uint32_t)hx | ((uint32_t)hy << 16));
}

// ---------------------------------------------------------------------------
// Kernel 0: split W fp32 -> bf16 hi/lo
// ---------------------------------------------------------------------------
__global__ void wsplit_kernel(const float* __restrict__ w,
                              __nv_bfloat16* __restrict__ hi,
                              __nv_bfloat16* __restrict__ lo, int n)
{
    int i = blockIdx.x * blockDim.x + threadIdx.x;
    if (i >= n) return;
    float a = w[i];
    __nv_bfloat16 h = __float2bfloat16(a);
    float r = a - __bfloat162float(h);
    hi[i] = h;
    lo[i] = __float2bfloat16(r);
}

// ---------------------------------------------------------------------------
// Kernel 1: gather + max over S. grid = (C, B), 256 threads.
// ---------------------------------------------------------------------------
__global__ __launch_bounds__(256) void sample_split_kernel(
    const float* __restrict__ feat, const uint2* __restrict__ pre,
    __nv_bfloat16* __restrict__ vhi, __nv_bfloat16* __restrict__ vlo,
    int C, int Wd, int ZX)
{
    extern __shared__ float sp[];
    const int c = blockIdx.x;
    const int b = blockIdx.y;
    const int HW = Wd * Wd;
    const int HWP = HW + 4;
    const int N = YVAL * ZX;

    for (int s = 0; s < SVAL; s++) {
        const float4* src = (const float4*)(feat + ((size_t)(b * SVAL + s) * C + c) * (size_t)HW);
        float4* dst = (float4*)(sp + s * HWP);
        for (int i = threadIdx.x; i < HW / 4; i += blockDim.x)
            dst[i] = src[i];
    }
    if (threadIdx.x < SVAL) sp[threadIdx.x * HWP + HW] = 0.0f;
    __syncthreads();

    size_t row = ((size_t)(b * C + c) * YVAL) * (size_t)ZX;
    __nv_bfloat16* __restrict__ oh = vhi + row;
    __nv_bfloat16* __restrict__ ol = vlo + row;

    for (int idx = threadIdx.x; idx < N; idx += blockDim.x) {
        float vmax = -INFINITY;
#pragma unroll
        for (int s = 0; s < SVAL; s++) {
            uint2 u = pre[(size_t)(b * SVAL + s) * N + idx];
            int a0 = u.x & 0x7FFF;
            int dx = (u.x >> 15) & 1;
            int a1 = u.x >> 16;
            float wx = __half2float(__ushort_as_half((unsigned short)(u.y & 0xFFFFu)));
            float wy = __half2float(__ushort_as_half((unsigned short)(u.y >> 16)));
            const float* pl = sp + s * HWP;
            float v00 = pl[a0];
            float v01 = pl[a0 + dx];
            float v10 = pl[a1];
            float v11 = pl[a1 + dx];
            float v0 = fmaf(wx, v01 - v00, v00);
            float v1 = fmaf(wx, v11 - v10, v10);
            float sm = fmaf(wy, v1 - v0, v0);
            vmax = fmaxf(vmax, sm);
        }
        __nv_bfloat16 h = __float2bfloat16(vmax);
        float r = vmax - __bfloat162float(h);
        oh[idx] = h;
        ol[idx] = __float2bfloat16(r);
    }
}

// ---------------------------------------------------------------------------
// Kernel 2: mma.sync bf16 GEMM + bias + silu.
// <64,128> BK=64, 2-stage cp.async (2 CTAs/SM), warp grid 2x4 (MT=2,NT=4),
// frag double buffer, pass-major order.
// ---------------------------------------------------------------------------
__global__ __launch_bounds__(256, 2) void gemm_mma_kernel(
    const __nv_bfloat16* __restrict__ Whi, const __nv_bfloat16* __restrict__ Wlo,
    const __nv_bfloat16* __restrict__ Vhi, const __nv_bfloat16* __restrict__ Vlo,
    const float* __restrict__ bias, float* __restrict__ out,
    int M, int N, int K)
{
    constexpr int BM = 64, BN = 128, BK = 64;
    constexpr int WTM = BM / 2;          // 32
    constexpr int WTN = BN / 4;          // 32
    constexpr int MT = WTM / 16;         // 2
    constexpr int NT = WTN / 8;          // 4
    constexpr int ARB = BK * 2;          // 128
    constexpr int CA  = BK / 8;          // 8
    constexpr int A_PLANE = BM * ARB;    // 16384 bytes? no: 64*128 = 8192
    constexpr int B_PLANE = BK * BN * 2; // 16384
    constexpr int BRB = BN * 2;          // 256
    constexpr int CB  = BN / 8;          // 16
    constexpr int STAGE = 2 * A_PLANE + 2 * B_PLANE;  // 49152

    extern __shared__ char smraw[];
    uint32_t sb = (smem_u32(smraw) + 1023u) & ~1023u;

    const int bn = blockIdx.x * BN;
    const int bm = blockIdx.y * BM;
    const int z  = blockIdx.z;
    const int tid = threadIdx.x;
    const int lane = tid & 31;
    const int wid = tid >> 5;
    const int wm = wid & 1;              // 2 in m
    const int wn = wid >> 1;             // 4 in n

    const __nv_bfloat16* __restrict__ Vhb = Vhi + (size_t)z * (size_t)K * (size_t)N;
    const __nv_bfloat16* __restrict__ Vlb = Vlo + (size_t)z * (size_t)K * (size_t)N;

    float acc[MT][NT][4];
#pragma unroll
    for (int i = 0; i < MT; i++)
#pragma unroll
        for (int j = 0; j < NT; j++)
#pragma unroll
            for (int q = 0; q < 4; q++) acc[i][j][q] = 0.0f;

    const int NC = K / BK;

    auto load_chunk = [&](int c, int s) {
        uint32_t st = sb + (uint32_t)s * STAGE;
        const int k0 = c * BK;
#pragma unroll 2
        for (int i = tid; i < BM * CA; i += 256) {
            int r = i / CA, ch = i % CA;
            uint32_t off = (uint32_t)(r * ARB + ((ch ^ (r & (CA - 1))) << 4));
            size_t g = (size_t)(bm + r) * (size_t)K + (size_t)(k0 + ch * 8);
            cp16(st + off, Whi + g);
            cp16(st + A_PLANE + off, Wlo + g);
        }
#pragma unroll 4
        for (int i = tid; i < BK * CB; i += 256) {
            int r = i / CB, ch = i % CB;
            uint32_t off = (uint32_t)(r * BRB + ((ch ^ (r & 7)) << 4));
            size_t g = (size_t)(k0 + r) * (size_t)N + (size_t)(bn + ch * 8);
            cp16(st + 2 * A_PLANE + off, Vhb + g);
            cp16(st + 2 * A_PLANE + B_PLANE + off, Vlb + g);
        }
    };

    load_chunk(0, 0); CP_COMMIT();
    if (NC > 1) load_chunk(1, 1);
    CP_COMMIT();

    uint32_t ahi[2][MT][4], alo[2][MT][4];
    uint32_t bhi[2][NT][2], blo[2][NT][2];

    for (int c = 0; c < NC; c++) {
        CP_WAIT1();
        __syncthreads();

        uint32_t st = sb + (uint32_t)(c & 1) * STAGE;
        uint32_t Ah = st, Al = st + A_PLANE;
        uint32_t Bh = st + 2 * A_PLANE, Bl = Bh + B_PLANE;

        auto load_frags = [&](int ks, int pb) {
#pragma unroll
            for (int mt = 0; mt < MT; mt++) {
                int r = wm * WTM + mt * 16 + (lane & 15);
                int ch = ks * 2 + (lane >> 4);
                uint32_t off = (uint32_t)(r * ARB + ((ch ^ (r & (CA - 1))) << 4));
                ldsm4(ahi[pb][mt], Ah + off);
                ldsm4(alo[pb][mt], Al + off);
            }
#pragma unroll
            for (int nt2 = 0; nt2 < NT / 2; nt2++) {
                int r = ks * 16 + (lane & 15);
                int ch = wn * NT + nt2 * 2 + (lane >> 4);
                uint32_t off = (uint32_t)(r * BRB + ((ch ^ (r & 7)) << 4));
                uint32_t t[4];
                ldsm4t(t, Bh + off);
                bhi[pb][nt2 * 2][0] = t[0]; bhi[pb][nt2 * 2][1] = t[1];
                bhi[pb][nt2 * 2 + 1][0] = t[2]; bhi[pb][nt2 * 2 + 1][1] = t[3];
                ldsm4t(t, Bl + off);
                blo[pb][nt2 * 2][0] = t[0]; blo[pb][nt2 * 2][1] = t[1];
                blo[pb][nt2 * 2 + 1][0] = t[2]; blo[pb][nt2 * 2 + 1][1] = t[3];
            }
        };

        load_frags(0, 0);
#pragma unroll
        for (int ks = 0; ks < BK / 16; ks++) {
            if (ks + 1 < BK / 16) load_frags(ks + 1, (ks + 1) & 1);
            int pb = ks & 1;
#pragma unroll
            for (int mt = 0; mt < MT; mt++)
#pragma unroll
                for (int nt = 0; nt < NT; nt++)
                    mma16816(acc[mt][nt], ahi[pb][mt], bhi[pb][nt]);
#pragma unroll
            for (int mt = 0; mt < MT; mt++)
#pragma unroll
                for (int nt = 0; nt < NT; nt++)
                    mma16816(acc[mt][nt], ahi[pb][mt], blo[pb][nt]);
#pragma unroll
            for (int mt = 0; mt < MT; mt++)
#pragma unroll
                for (int nt = 0; nt < NT; nt++)
                    mma16816(acc[mt][nt], alo[pb][mt], bhi[pb][nt]);
        }
        __syncthreads();

        if (c + 2 < NC) load_chunk(c + 2, c & 1);
        CP_COMMIT();
    }

    float* ob = out + (size_t)z * (size_t)M * (size_t)N;
#pragma unroll
    for (int mt = 0; mt < MT; mt++) {
        int row0 = bm + wm * WTM + mt * 16 + (lane >> 2);
        float bs0 = bias[row0];
        float bs1 = bias[row0 + 8];
#pragma unroll
        for (int nt = 0; nt < NT; nt++) {
            int col = bn + wn * WTN + nt * 8 + (lane & 3) * 2;
            float x0 = acc[mt][nt][0] + bs0;
            float x1 = acc[mt][nt][1] + bs0;
            float x2 = acc[mt][nt][2] + bs1;
            float x3 = acc[mt][nt][3] + bs1;
            float2 r0 = make_float2(x0 / (1.0f + expf(-x0)), x1 / (1.0f + expf(-x1)));
            float2 r1 = make_float2(x2 / (1.0f + expf(-x2)), x3 / (1.0f + expf(-x3)));
            *(float2*)&ob[(size_t)row0 * N + col] = r0;
            *(float2*)&ob[(size_t)(row0 + 8) * N + col] = r1;
        }
    }
}

// ---------------------------------------------------------------------------
// Kernel 3: valid voxel mask from scale-2 coords.
// ---------------------------------------------------------------------------
__global__ void mask_kernel(const float* __restrict__ coords,
                            float* __restrict__ out, int N)
{
    int i = blockIdx.x * blockDim.x + threadIdx.x;
    if (i >= BVAL * N) return;
    int b = i / N;
    int n = i % N;
    const float2* __restrict__ crd = (const float2*)coords;
    float m = 0.0f;
#pragma unroll
    for (int s = 0; s < SVAL; s++) {
        float2 g = crd[(size_t)(b * SVAL + s) * N + n];
        bool valid = (g.x >= -1.0f) & (g.x <= 1.0f) & (g.y >= -1.0f) & (g.y <= 1.0f);
        if (valid) m = 1.0f;
    }
    out[i] = m;
}

// ---------------------------------------------------------------------------
// launch
// ---------------------------------------------------------------------------
extern "C" void kernel_launch(void* const* d_in, const int* in_sizes, int n_in,
                              void* d_out, int out_size)
{
    const float* x3 = (const float*)d_in[0];
    const float* x4 = (const float*)d_in[1];
    const float* x5 = (const float*)d_in[2];
    const float* c2 = (const float*)d_in[3];
    const float* c4 = (const float*)d_in[4];
    const float* c8 = (const float*)d_in[5];
    const float* w2 = (const float*)d_in[6];
    const float* b2 = (const float*)d_in[7];
    const float* w4 = (const float*)d_in[8];
    const float* b4 = (const float*)d_in[9];
    const float* w8 = (const float*)d_in[10];
    const float* b8 = (const float*)d_in[11];

    float* out = (float*)d_out;

    __nv_bfloat16 *v2h, *v2l, *v4h, *v4l, *v8h, *v8l;
    __nv_bfloat16 *w2h, *w2l, *w4h, *w4l, *w8h, *w8l;
    uint2 *p2, *p4, *p8;
    cudaGetSymbolAddress((void**)&v2h, g_v2hi);
    cudaGetSymbolAddress((void**)&v2l, g_v2lo);
    cudaGetSymbolAddress((void**)&v4h, g_v4hi);
    cudaGetSymbolAddress((void**)&v4l, g_v4lo);
    cudaGetSymbolAddress((void**)&v8h, g_v8hi);
    cudaGetSymbolAddress((void**)&v8l, g_v8lo);
    cudaGetSymbolAddress((void**)&w2h, g_w2hi);
    cudaGetSymbolAddress((void**)&w2l, g_w2lo);
    cudaGetSymbolAddress((void**)&w4h, g_w4hi);
    cudaGetSymbolAddress((void**)&w4l, g_w4lo);
    cudaGetSymbolAddress((void**)&w8h, g_w8hi);
    cudaGetSymbolAddress((void**)&w8l, g_w8lo);
    cudaGetSymbolAddress((void**)&p2, g_pre2);
    cudaGetSymbolAddress((void**)&p4, g_pre4);
    cudaGetSymbolAddress((void**)&p8, g_pre8);

    const int smG = 2 * (2 * 64 * 128 + 2 * 64 * 128 * 2) + 1024;
    const int smS2 = 4 * (64 * 64 + 4) * 4;
    const int smS4 = 4 * (32 * 32 + 4) * 4;
    const int smS8 = 4 * (16 * 16 + 4) * 4;

    static bool s_init = false;
    static cudaStream_t st[3];
    static cudaEvent_t evRoot, evDone[3];
    if (!s_init) {
        for (int i = 0; i < 3; i++)
            cudaStreamCreateWithFlags(&st[i], cudaStreamNonBlocking);
        cudaEventCreateWithFlags(&evRoot, cudaEventDisableTiming);
        for (int i = 0; i < 3; i++)
            cudaEventCreateWithFlags(&evDone[i], cudaEventDisableTiming);
        cudaFuncSetAttribute(sample_split_kernel,
                             cudaFuncAttributeMaxDynamicSharedMemorySize, 66000);
        cudaFuncSetAttribute(gemm_mma_kernel,
                             cudaFuncAttributeMaxDynamicSharedMemorySize, smG);
        s_init = true;
    }

    const size_t off_bev2 = 0;
    const size_t off_bev4 = off_bev2 + 2ULL * 256 * 4096;
    const size_t off_bev8 = off_bev4 + 2ULL * 512 * 1024;
    const size_t off_mask = off_bev8 + 2ULL * 1024 * 256;

    cudaEventRecord(evRoot, 0);
    for (int i = 0; i < 3; i++) cudaStreamWaitEvent(st[i], evRoot, 0);

    // ---- chain 0: scale 2 ----
    precomp_kernel<<<(8 * 16384 + 255) / 256, 256, 0, st[0]>>>(c2, p2, 64, 8 * 16384);
    wsplit_kernel<<<(256 * 1024 + 255) / 256, 256, 0, st[0]>>>(w2, w2h, w2l, 256 * 1024);
    sample_split_kernel<<<dim3(256, BVAL), 256, smS2, st[0]>>>(x3, p2, v2h, v2l, 256, 64, 4096);
    gemm_mma_kernel<<<dim3(4096 / 128, 256 / 64, BVAL), 256, smG, st[0]>>>(
        w2h, w2l, v2h, v2l, b2, out + off_bev2, 256, 4096, 1024);

    // ---- chain 1: scale 4 ----
    precomp_kernel<<<(8 * 4096 + 255) / 256, 256, 0, st[1]>>>(c4, p4, 32, 8 * 4096);
    wsplit_kernel<<<(512 * 2048 + 255) / 256, 256, 0, st[1]>>>(w4, w4h, w4l, 512 * 2048);
    sample_split_kernel<<<dim3(512, BVAL), 256, smS4, st[1]>>>(x4, p4, v4h, v4l, 512, 32, 1024);
    gemm_mma_kernel<<<dim3(1024 / 128, 512 / 64, BVAL), 256, smG, st[1]>>>(
        w4h, w4l, v4h, v4l, b4, out + off_bev4, 512, 1024, 2048);

    // ---- chain 2: scale 8 ----
    precomp_kernel<<<(8 * 1024 + 255) / 256, 256, 0, st[2]>>>(c8, p8, 16, 8 * 1024);
    wsplit_kernel<<<(1024 * 4096 + 255) / 256, 256, 0, st[2]>>>(w8, w8h, w8l, 1024 * 4096);
    sample_split_kernel<<<dim3(1024, BVAL), 256, smS8, st[2]>>>(x5, p8, v8h, v8l, 1024, 16, 256);
    gemm_mma_kernel<<<dim3(256 / 128, 1024 / 64, BVAL), 256, smG, st[2]>>>(
        w8h, w8l, v8h, v8l, b8, out + off_bev8, 1024, 256, 4096);

    // mask on the capture stream (independent)
    mask_kernel<<<(BVAL * 16384 + 255) / 256, 256>>>(c2, out + off_mask, 16384);

    for (int i = 0; i < 3; i++) {
        cudaEventRecord(evDone[i], st[i]);
        cudaStreamWaitEvent(0, evDone[i], 0);
    }
}

// round 14
// speedup vs baseline: 1.1161x; 1.1161x over previous
#include <cuda_runtime.h>
#include <cuda_bf16.h>
#include <cuda_fp16.h>
#include <cstdint>
#include <math.h>

// ---------------------------------------------------------------------------
// IPMTrans round 14:
//   precomp    -> 16B descriptors (fp32 weights, reverted from fp16)
//   sampler    -> CHANNEL-PAIR packed planes: one gather serves 2 channels
//                 (half2 for scale2, float2 lossless for scale4/8)
//   GEMM       -> R13: <64,128> BK=64, 2-stage cp.async, warp grid 2x4
//   3 streams  -> per-scale chains
// ---------------------------------------------------------------------------

#define BVAL 2
#define SVAL 4
#define YVAL 4

// ------------------------- scratch (device globals) ------------------------
__device__ __align__(16) __nv_bfloat16 g_v2hi[2u * 1024u * 4096u];
__device__ __align__(16) __nv_bfloat16 g_v2lo[2u * 1024u * 4096u];
__device__ __align__(16) __nv_bfloat16 g_v4hi[2u * 2048u * 1024u];
__device__ __align__(16) __nv_bfloat16 g_v4lo[2u * 2048u * 1024u];
__device__ __align__(16) __nv_bfloat16 g_v8hi[2u * 4096u * 256u];
__device__ __align__(16) __nv_bfloat16 g_v8lo[2u * 4096u * 256u];
__device__ __align__(16) __nv_bfloat16 g_w2hi[256u * 1024u];
__device__ __align__(16) __nv_bfloat16 g_w2lo[256u * 1024u];
__device__ __align__(16) __nv_bfloat16 g_w4hi[512u * 2048u];
__device__ __align__(16) __nv_bfloat16 g_w4lo[512u * 2048u];
__device__ __align__(16) __nv_bfloat16 g_w8hi[1024u * 4096u];
__device__ __align__(16) __nv_bfloat16 g_w8lo[1024u * 4096u];
__device__ __align__(16) uint4 g_pre2[8u * 16384u];
__device__ __align__(16) uint4 g_pre4[8u * 4096u];
__device__ __align__(16) uint4 g_pre8[8u * 1024u];

// ------------------------- PTX helpers -------------------------------------
__device__ __forceinline__ uint32_t smem_u32(const void* p) {
    uint32_t a;
    asm("{ .reg .u64 t; cvta.to.shared.u64 t, %1; cvt.u32.u64 %0, t; }" : "=r"(a) : "l"(p));
    return a;
}
__device__ __forceinline__ void cp16(uint32_t dst, const void* src) {
    asm volatile("cp.async.cg.shared.global [%0], [%1], 16;" :: "r"(dst), "l"(src));
}
#define CP_COMMIT() asm volatile("cp.async.commit_group;" ::: "memory")
#define CP_WAIT1()  asm volatile("cp.async.wait_group 1;" ::: "memory")

__device__ __forceinline__ void ldsm4(uint32_t* r, uint32_t addr) {
    asm volatile("ldmatrix.sync.aligned.m8n8.x4.shared.b16 {%0,%1,%2,%3}, [%4];"
        : "=r"(r[0]), "=r"(r[1]), "=r"(r[2]), "=r"(r[3]) : "r"(addr));
}
__device__ __forceinline__ void ldsm4t(uint32_t* r, uint32_t addr) {
    asm volatile("ldmatrix.sync.aligned.m8n8.x4.trans.shared.b16 {%0,%1,%2,%3}, [%4];"
        : "=r"(r[0]), "=r"(r[1]), "=r"(r[2]), "=r"(r[3]) : "r"(addr));
}
__device__ __forceinline__ void mma16816(float* d, const uint32_t* a, const uint32_t* b) {
    asm volatile(
        "mma.sync.aligned.m16n8k16.row.col.f32.bf16.bf16.f32 "
        "{%0,%1,%2,%3}, {%4,%5,%6,%7}, {%8,%9}, {%0,%1,%2,%3};"
        : "+f"(d[0]), "+f"(d[1]), "+f"(d[2]), "+f"(d[3])
        : "r"(a[0]), "r"(a[1]), "r"(a[2]), "r"(a[3]), "r"(b[0]), "r"(b[1]));
}

// channel-pair pack policies
struct PackF16 {
    using T = __half2;
    static __device__ __forceinline__ T pack(float a, float b) { return __floats2half2_rn(a, b); }
    static __device__ __forceinline__ float2 unpack(T v) { return __half22float2(v); }
};
struct PackF32 {
    using T = float2;
    static __device__ __forceinline__ T pack(float a, float b) { return make_float2(a, b); }
    static __device__ __forceinline__ float2 unpack(T v) { return v; }
};

// ---------------------------------------------------------------------------
// Kernel P: precompute 16B gather descriptors (fp32 weights).
//   pre.x = a0 | dx<<15 | a1<<16 ; sentinel HW when invalid, wx=wy=0
// ---------------------------------------------------------------------------
__global__ void precomp_kernel(const float* __restrict__ coords,
                               uint4* __restrict__ pre,
                               int Wd, int total)
{
    int i = blockIdx.x * blockDim.x + threadIdx.x;
    if (i >= total) return;
    float2 g = ((const float2*)coords)[i];
    const int HW = Wd * Wd;
    const float sc = 0.5f * (float)(Wd - 1);

    float ix = (g.x + 1.0f) * sc;
    float iy = (g.y + 1.0f) * sc;
    float x0f = floorf(ix);
    float y0f = floorf(iy);
    float wx = ix - x0f;
    float wy = iy - y0f;
    int x0 = min(max((int)x0f, 0), Wd - 1);
    int y0 = min(max((int)y0f, 0), Wd - 1);
    int x1 = min(x0 + 1, Wd - 1);
    int y1 = min(y0 + 1, Wd - 1);
    bool valid = (g.x >= -1.0f) & (g.x <= 1.0f) & (g.y >= -1.0f) & (g.y <= 1.0f);

    int a0 = y0 * Wd + x0;
    int a1 = y1 * Wd + x0;
    int dx = x1 - x0;
    if (!valid) { a0 = HW; a1 = HW; dx = 0; wx = 0.0f; wy = 0.0f; }

    pre[i] = make_uint4((uint32_t)a0 | ((uint32_t)dx << 15) | ((uint32_t)a1 << 16),
                        __float_as_uint(wx), __float_as_uint(wy), 0u);
}

// ---------------------------------------------------------------------------
// Kernel 0: split W fp32 -> bf16 hi/lo
// ---------------------------------------------------------------------------
__global__ void wsplit_kernel(const float* __restrict__ w,
                              __nv_bfloat16* __restrict__ hi,
                              __nv_bfloat16* __restrict__ lo, int n)
{
    int i = blockIdx.x * blockDim.x + threadIdx.x;
    if (i >= n) return;
    float a = w[i];
    __nv_bfloat16 h = __float2bfloat16(a);
    float r = a - __bfloat162float(h);
    hi[i] = h;
    lo[i] = __float2bfloat16(r);
}

// ---------------------------------------------------------------------------
// Kernel 1: channel-pair gather + max over S.
// grid = (C/2, B), 256 threads. One gather serves both channels of the pair.
// ---------------------------------------------------------------------------
template <class PK>
__global__ __launch_bounds__(256) void sample_pair_kernel(
    const float* __restrict__ feat, const uint4* __restrict__ pre,
    __nv_bfloat16* __restrict__ vhi, __nv_bfloat16* __restrict__ vlo,
    int C, int Wd, int ZX)
{
    using T = typename PK::T;
    extern __shared__ char smraw[];
    T* sp = (T*)smraw;

    const int c0 = blockIdx.x * 2;
    const int b = blockIdx.y;
    const int HW = Wd * Wd;
    const int HWP = HW + 4;
    const int N = YVAL * ZX;

    // stage 4 s-planes, each holding the channel pair
    for (int s = 0; s < SVAL; s++) {
        const float4* p0 = (const float4*)(feat + ((size_t)(b * SVAL + s) * C + c0) * (size_t)HW);
        const float4* p1 = (const float4*)(feat + ((size_t)(b * SVAL + s) * C + c0 + 1) * (size_t)HW);
        T* dst = sp + s * HWP;
        for (int i = threadIdx.x; i < HW / 4; i += blockDim.x) {
            float4 A = p0[i];
            float4 B = p1[i];
            dst[i * 4 + 0] = PK::pack(A.x, B.x);
            dst[i * 4 + 1] = PK::pack(A.y, B.y);
            dst[i * 4 + 2] = PK::pack(A.z, B.z);
            dst[i * 4 + 3] = PK::pack(A.w, B.w);
        }
    }
    if (threadIdx.x < SVAL) sp[threadIdx.x * HWP + HW] = PK::pack(0.0f, 0.0f);
    __syncthreads();

    size_t row0 = ((size_t)(b * C + c0) * YVAL) * (size_t)ZX;
    size_t row1 = row0 + (size_t)YVAL * ZX;

    for (int idx = threadIdx.x; idx < N; idx += blockDim.x) {
        float vmax0 = -INFINITY, vmax1 = -INFINITY;
#pragma unroll
        for (int s = 0; s < SVAL; s++) {
            uint4 u = pre[(size_t)(b * SVAL + s) * N + idx];
            int a0 = u.x & 0x7FFF;
            int dx = (u.x >> 15) & 1;
            int a1 = u.x >> 16;
            float wx = __uint_as_float(u.y);
            float wy = __uint_as_float(u.z);
            const T* pl = sp + s * HWP;
            float2 q00 = PK::unpack(pl[a0]);
            float2 q01 = PK::unpack(pl[a0 + dx]);
            float2 q10 = PK::unpack(pl[a1]);
            float2 q11 = PK::unpack(pl[a1 + dx]);
            // channel 0
            float v0 = fmaf(wx, q01.x - q00.x, q00.x);
            float v1 = fmaf(wx, q11.x - q10.x, q10.x);
            vmax0 = fmaxf(vmax0, fmaf(wy, v1 - v0, v0));
            // channel 1
            float u0 = fmaf(wx, q01.y - q00.y, q00.y);
            float u1 = fmaf(wx, q11.y - q10.y, q10.y);
            vmax1 = fmaxf(vmax1, fmaf(wy, u1 - u0, u0));
        }
        __nv_bfloat16 h0 = __float2bfloat16(vmax0);
        vhi[row0 + idx] = h0;
        vlo[row0 + idx] = __float2bfloat16(vmax0 - __bfloat162float(h0));
        __nv_bfloat16 h1 = __float2bfloat16(vmax1);
        vhi[row1 + idx] = h1;
        vlo[row1 + idx] = __float2bfloat16(vmax1 - __bfloat162float(h1));
    }
}

// ---------------------------------------------------------------------------
// Kernel 2: mma.sync bf16 GEMM + bias + silu (R13: 2x4 warp grid).
// ---------------------------------------------------------------------------
__global__ __launch_bounds__(256, 2) void gemm_mma_kernel(
    const __nv_bfloat16* __restrict__ Whi, const __nv_bfloat16* __restrict__ Wlo,
    const __nv_bfloat16* __restrict__ Vhi, const __nv_bfloat16* __restrict__ Vlo,
    const float* __restrict__ bias, float* __restrict__ out,
    int M, int N, int K)
{
    constexpr int BM = 64, BN = 128, BK = 64;
    constexpr int WTM = BM / 2;          // 32
    constexpr int WTN = BN / 4;          // 32
    constexpr int MT = WTM / 16;         // 2
    constexpr int NT = WTN / 8;          // 4
    constexpr int ARB = BK * 2;
    constexpr int CA  = BK / 8;
    constexpr int A_PLANE = BM * ARB;    // 8192
    constexpr int B_PLANE = BK * BN * 2; // 16384
    constexpr int BRB = BN * 2;
    constexpr int CB  = BN / 8;
    constexpr int STAGE = 2 * A_PLANE + 2 * B_PLANE;  // 49152

    extern __shared__ char smraw[];
    uint32_t sb = (smem_u32(smraw) + 1023u) & ~1023u;

    const int bn = blockIdx.x * BN;
    const int bm = blockIdx.y * BM;
    const int z  = blockIdx.z;
    const int tid = threadIdx.x;
    const int lane = tid & 31;
    const int wid = tid >> 5;
    const int wm = wid & 1;
    const int wn = wid >> 1;

    const __nv_bfloat16* __restrict__ Vhb = Vhi + (size_t)z * (size_t)K * (size_t)N;
    const __nv_bfloat16* __restrict__ Vlb = Vlo + (size_t)z * (size_t)K * (size_t)N;

    float acc[MT][NT][4];
#pragma unroll
    for (int i = 0; i < MT; i++)
#pragma unroll
        for (int j = 0; j < NT; j++)
#pragma unroll
            for (int q = 0; q < 4; q++) acc[i][j][q] = 0.0f;

    const int NC = K / BK;

    auto load_chunk = [&](int c, int s) {
        uint32_t st = sb + (uint32_t)s * STAGE;
        const int k0 = c * BK;
#pragma unroll 2
        for (int i = tid; i < BM * CA; i += 256) {
            int r = i / CA, ch = i % CA;
            uint32_t off = (uint32_t)(r * ARB + ((ch ^ (r & (CA - 1))) << 4));
            size_t g = (size_t)(bm + r) * (size_t)K + (size_t)(k0 + ch * 8);
            cp16(st + off, Whi + g);
            cp16(st + A_PLANE + off, Wlo + g);
        }
#pragma unroll 4
        for (int i = tid; i < BK * CB; i += 256) {
            int r = i / CB, ch = i % CB;
            uint32_t off = (uint32_t)(r * BRB + ((ch ^ (r & 7)) << 4));
            size_t g = (size_t)(k0 + r) * (size_t)N + (size_t)(bn + ch * 8);
            cp16(st + 2 * A_PLANE + off, Vhb + g);
            cp16(st + 2 * A_PLANE + B_PLANE + off, Vlb + g);
        }
    };

    load_chunk(0, 0); CP_COMMIT();
    if (NC > 1) load_chunk(1, 1);
    CP_COMMIT();

    uint32_t ahi[2][MT][4], alo[2][MT][4];
    uint32_t bhi[2][NT][2], blo[2][NT][2];

    for (int c = 0; c < NC; c++) {
        CP_WAIT1();
        __syncthreads();

        uint32_t st = sb + (uint32_t)(c & 1) * STAGE;
        uint32_t Ah = st, Al = st + A_PLANE;
        uint32_t Bh = st + 2 * A_PLANE, Bl = Bh + B_PLANE;

        auto load_frags = [&](int ks, int pb) {
#pragma unroll
            for (int mt = 0; mt < MT; mt++) {
                int r = wm * WTM + mt * 16 + (lane & 15);
                int ch = ks * 2 + (lane >> 4);
                uint32_t off = (uint32_t)(r * ARB + ((ch ^ (r & (CA - 1))) << 4));
                ldsm4(ahi[pb][mt], Ah + off);
                ldsm4(alo[pb][mt], Al + off);
            }
#pragma unroll
            for (int nt2 = 0; nt2 < NT / 2; nt2++) {
                int r = ks * 16 + (lane & 15);
                int ch = wn * NT + nt2 * 2 + (lane >> 4);
                uint32_t off = (uint32_t)(r * BRB + ((ch ^ (r & 7)) << 4));
                uint32_t t[4];
                ldsm4t(t, Bh + off);
                bhi[pb][nt2 * 2][0] = t[0]; bhi[pb][nt2 * 2][1] = t[1];
                bhi[pb][nt2 * 2 + 1][0] = t[2]; bhi[pb][nt2 * 2 + 1][1] = t[3];
                ldsm4t(t, Bl + off);
                blo[pb][nt2 * 2][0] = t[0]; blo[pb][nt2 * 2][1] = t[1];
                blo[pb][nt2 * 2 + 1][0] = t[2]; blo[pb][nt2 * 2 + 1][1] = t[3];
            }
        };

        load_frags(0, 0);
#pragma unroll
        for (int ks = 0; ks < BK / 16; ks++) {
            if (ks + 1 < BK / 16) load_frags(ks + 1, (ks + 1) & 1);
            int pb = ks & 1;
#pragma unroll
            for (int mt = 0; mt < MT; mt++)
#pragma unroll
                for (int nt = 0; nt < NT; nt++)
                    mma16816(acc[mt][nt], ahi[pb][mt], bhi[pb][nt]);
#pragma unroll
            for (int mt = 0; mt < MT; mt++)
#pragma unroll
                for (int nt = 0; nt < NT; nt++)
                    mma16816(acc[mt][nt], ahi[pb][mt], blo[pb][nt]);
#pragma unroll
            for (int mt = 0; mt < MT; mt++)
#pragma unroll
                for (int nt = 0; nt < NT; nt++)
                    mma16816(acc[mt][nt], alo[pb][mt], bhi[pb][nt]);
        }
        __syncthreads();

        if (c + 2 < NC) load_chunk(c + 2, c & 1);
        CP_COMMIT();
    }

    float* ob = out + (size_t)z * (size_t)M * (size_t)N;
#pragma unroll
    for (int mt = 0; mt < MT; mt++) {
        int row0 = bm + wm * WTM + mt * 16 + (lane >> 2);
        float bs0 = bias[row0];
        float bs1 = bias[row0 + 8];
#pragma unroll
        for (int nt = 0; nt < NT; nt++) {
            int col = bn + wn * WTN + nt * 8 + (lane & 3) * 2;
            float x0 = acc[mt][nt][0] + bs0;
            float x1 = acc[mt][nt][1] + bs0;
            float x2 = acc[mt][nt][2] + bs1;
            float x3 = acc[mt][nt][3] + bs1;
            float2 r0 = make_float2(x0 / (1.0f + expf(-x0)), x1 / (1.0f + expf(-x1)));
            float2 r1 = make_float2(x2 / (1.0f + expf(-x2)), x3 / (1.0f + expf(-x3)));
            *(float2*)&ob[(size_t)row0 * N + col] = r0;
            *(float2*)&ob[(size_t)(row0 + 8) * N + col] = r1;
        }
    }
}

// ---------------------------------------------------------------------------
// Kernel 3: valid voxel mask from scale-2 coords.
// ---------------------------------------------------------------------------
__global__ void mask_kernel(const float* __restrict__ coords,
                            float* __restrict__ out, int N)
{
    int i = blockIdx.x * blockDim.x + threadIdx.x;
    if (i >= BVAL * N) return;
    int b = i / N;
    int n = i % N;
    const float2* __restrict__ crd = (const float2*)coords;
    float m = 0.0f;
#pragma unroll
    for (int s = 0; s < SVAL; s++) {
        float2 g = crd[(size_t)(b * SVAL + s) * N + n];
        bool valid = (g.x >= -1.0f) & (g.x <= 1.0f) & (g.y >= -1.0f) & (g.y <= 1.0f);
        if (valid) m = 1.0f;
    }
    out[i] = m;
}

// ---------------------------------------------------------------------------
// launch
// ---------------------------------------------------------------------------
extern "C" void kernel_launch(void* const* d_in, const int* in_sizes, int n_in,
                              void* d_out, int out_size)
{
    const float* x3 = (const float*)d_in[0];
    const float* x4 = (const float*)d_in[1];
    const float* x5 = (const float*)d_in[2];
    const float* c2 = (const float*)d_in[3];
    const float* c4 = (const float*)d_in[4];
    const float* c8 = (const float*)d_in[5];
    const float* w2 = (const float*)d_in[6];
    const float* b2 = (const float*)d_in[7];
    const float* w4 = (const float*)d_in[8];
    const float* b4 = (const float*)d_in[9];
    const float* w8 = (const float*)d_in[10];
    const float* b8 = (const float*)d_in[11];

    float* out = (float*)d_out;

    __nv_bfloat16 *v2h, *v2l, *v4h, *v4l, *v8h, *v8l;
    __nv_bfloat16 *w2h, *w2l, *w4h, *w4l, *w8h, *w8l;
    uint4 *p2, *p4, *p8;
    cudaGetSymbolAddress((void**)&v2h, g_v2hi);
    cudaGetSymbolAddress((void**)&v2l, g_v2lo);
    cudaGetSymbolAddress((void**)&v4h, g_v4hi);
    cudaGetSymbolAddress((void**)&v4l, g_v4lo);
    cudaGetSymbolAddress((void**)&v8h, g_v8hi);
    cudaGetSymbolAddress((void**)&v8l, g_v8lo);
    cudaGetSymbolAddress((void**)&w2h, g_w2hi);
    cudaGetSymbolAddress((void**)&w2l, g_w2lo);
    cudaGetSymbolAddress((void**)&w4h, g_w4hi);
    cudaGetSymbolAddress((void**)&w4l, g_w4lo);
    cudaGetSymbolAddress((void**)&w8h, g_w8hi);
    cudaGetSymbolAddress((void**)&w8l, g_w8lo);
    cudaGetSymbolAddress((void**)&p2, g_pre2);
    cudaGetSymbolAddress((void**)&p4, g_pre4);
    cudaGetSymbolAddress((void**)&p8, g_pre8);

    const int smG = 2 * (2 * 64 * 128 + 2 * 64 * 128 * 2) + 1024;
    const int smS2 = 4 * (64 * 64 + 4) * (int)sizeof(__half2);   // 65600
    const int smS4 = 4 * (32 * 32 + 4) * (int)sizeof(float2);    // 32896
    const int smS8 = 4 * (16 * 16 + 4) * (int)sizeof(float2);    //  8320

    static bool s_init = false;
    static cudaStream_t st[3];
    static cudaEvent_t evRoot, evDone[3];
    if (!s_init) {
        for (int i = 0; i < 3; i++)
            cudaStreamCreateWithFlags(&st[i], cudaStreamNonBlocking);
        cudaEventCreateWithFlags(&evRoot, cudaEventDisableTiming);
        for (int i = 0; i < 3; i++)
            cudaEventCreateWithFlags(&evDone[i], cudaEventDisableTiming);
        cudaFuncSetAttribute(sample_pair_kernel<PackF16>,
                             cudaFuncAttributeMaxDynamicSharedMemorySize, 66000);
        cudaFuncSetAttribute(gemm_mma_kernel,
                             cudaFuncAttributeMaxDynamicSharedMemorySize, smG);
        s_init = true;
    }

    const size_t off_bev2 = 0;
    const size_t off_bev4 = off_bev2 + 2ULL * 256 * 4096;
    const size_t off_bev8 = off_bev4 + 2ULL * 512 * 1024;
    const size_t off_mask = off_bev8 + 2ULL * 1024 * 256;

    cudaEventRecord(evRoot, 0);
    for (int i = 0; i < 3; i++) cudaStreamWaitEvent(st[i], evRoot, 0);

    // ---- chain 0: scale 2 (half2 pairs) ----
    precomp_kernel<<<(8 * 16384 + 255) / 256, 256, 0, st[0]>>>(c2, p2, 64, 8 * 16384);
    wsplit_kernel<<<(256 * 1024 + 255) / 256, 256, 0, st[0]>>>(w2, w2h, w2l, 256 * 1024);
    sample_pair_kernel<PackF16><<<dim3(256 / 2, BVAL), 256, smS2, st[0]>>>(
        x3, p2, v2h, v2l, 256, 64, 4096);
    gemm_mma_kernel<<<dim3(4096 / 128, 256 / 64, BVAL), 256, smG, st[0]>>>(
        w2h, w2l, v2h, v2l, b2, out + off_bev2, 256, 4096, 1024);

    // ---- chain 1: scale 4 (float2 pairs, lossless) ----
    precomp_kernel<<<(8 * 4096 + 255) / 256, 256, 0, st[1]>>>(c4, p4, 32, 8 * 4096);
    wsplit_kernel<<<(512 * 2048 + 255) / 256, 256, 0, st[1]>>>(w4, w4h, w4l, 512 * 2048);
    sample_pair_kernel<PackF32><<<dim3(512 / 2, BVAL), 256, smS4, st[1]>>>(
        x4, p4, v4h, v4l, 512, 32, 1024);
    gemm_mma_kernel<<<dim3(1024 / 128, 512 / 64, BVAL), 256, smG, st[1]>>>(
        w4h, w4l, v4h, v4l, b4, out + off_bev4, 512, 1024, 2048);

    // ---- chain 2: scale 8 (float2 pairs, lossless) ----
    precomp_kernel<<<(8 * 1024 + 255) / 256, 256, 0, st[2]>>>(c8, p8, 16, 8 * 1024);
    wsplit_kernel<<<(1024 * 4096 + 255) / 256, 256, 0, st[2]>>>(w8, w8h, w8l, 1024 * 4096);
    sample_pair_kernel<PackF32><<<dim3(1024 / 2, BVAL), 256, smS8, st[2]>>>(
        x5, p8, v8h, v8l, 1024, 16, 256);
    gemm_mma_kernel<<<dim3(256 / 128, 1024 / 64, BVAL), 256, smG, st[2]>>>(
        w8h, w8l, v8h, v8l, b8, out + off_bev8, 1024, 256, 4096);

    // mask on the capture stream (independent)
    mask_kernel<<<(BVAL * 16384 + 255) / 256, 256>>>(c2, out + off_mask, 16384);

    for (int i = 0; i < 3; i++) {
        cudaEventRecord(evDone[i], st[i]);
        cudaStreamWaitEvent(0, evDone[i], 0);
    }
}